// round 2
// baseline (speedup 1.0000x reference)
#include <cuda_runtime.h>

// out[i] = in[i,1] + w*(in[i,0]-in[i,1])
// N = 16777216. Pure streaming, 12 B/elem traffic.
// 8 outputs per thread: 4 independent LDG.128 (streaming), 2 STG.128 (streaming).

__global__ __launch_bounds__(256)
void skip_kernel(const float4* __restrict__ in,
                 const float* __restrict__ w_ptr,
                 float4* __restrict__ out)
{
    const unsigned i = blockIdx.x * blockDim.x + threadIdx.x;
    const float w = __ldg(w_ptr);

    // 8 outputs = 16 input floats = four float4 loads, front-batched.
    const unsigned base = 4u * i;
    float4 a = __ldcs(&in[base + 0u]);
    float4 b = __ldcs(&in[base + 1u]);
    float4 c = __ldcs(&in[base + 2u]);
    float4 d = __ldcs(&in[base + 3u]);

    float4 o0, o1;
    o0.x = fmaf(w, a.x - a.y, a.y);
    o0.y = fmaf(w, a.z - a.w, a.w);
    o0.z = fmaf(w, b.x - b.y, b.y);
    o0.w = fmaf(w, b.z - b.w, b.w);
    o1.x = fmaf(w, c.x - c.y, c.y);
    o1.y = fmaf(w, c.z - c.w, c.w);
    o1.z = fmaf(w, d.x - d.y, d.y);
    o1.w = fmaf(w, d.z - d.w, d.w);

    __stcs(&out[2u * i + 0u], o0);
    __stcs(&out[2u * i + 1u], o1);
}

extern "C" void kernel_launch(void* const* d_in, const int* in_sizes, int n_in,
                              void* d_out, int out_size)
{
    const float* input  = (const float*)d_in[0];   // [N,2]
    const float* weight = (const float*)d_in[1];   // [1,1]
    float*       out    = (float*)d_out;           // [N,1]

    const int n = in_sizes[0] / 2;     // 16777216 outputs
    const int n8 = n / 8;              // 8 outputs per thread, exact
    const int threads = 256;
    const int blocks = n8 / threads;   // 8192

    skip_kernel<<<blocks, threads>>>((const float4*)input, weight, (float4*)out);
}

// round 3
// speedup vs baseline: 1.0381x; 1.0381x over previous
#include <cuda_runtime.h>

// out[i] = in[i,1] + w*(in[i,0]-in[i,1])
// N = 16777216. Pure streaming, 12 B/elem.
// R1 shape (best: 27.1us, DRAM 78%): 4 outputs/thread, two LDG.128.
// Only delta vs R1: streaming store hint (__stcs) — output is never re-read.

__global__ __launch_bounds__(256)
void skip_kernel(const float4* __restrict__ in,
                 const float* __restrict__ w_ptr,
                 float4* __restrict__ out)
{
    const unsigned i = blockIdx.x * blockDim.x + threadIdx.x;
    const float w = __ldg(w_ptr);

    float4 a = __ldg(&in[2u * i]);
    float4 b = __ldg(&in[2u * i + 1u]);

    float4 o;
    o.x = fmaf(w, a.x - a.y, a.y);
    o.y = fmaf(w, a.z - a.w, a.w);
    o.z = fmaf(w, b.x - b.y, b.y);
    o.w = fmaf(w, b.z - b.w, b.w);

    __stcs(&out[i], o);
}

extern "C" void kernel_launch(void* const* d_in, const int* in_sizes, int n_in,
                              void* d_out, int out_size)
{
    const float* input  = (const float*)d_in[0];   // [N,2]
    const float* weight = (const float*)d_in[1];   // [1,1]
    float*       out    = (float*)d_out;           // [N,1]

    const int n = in_sizes[0] / 2;     // 16777216 outputs
    const int n4 = n / 4;              // 4 outputs per thread, exact
    const int threads = 256;
    const int blocks = n4 / threads;   // 16384

    skip_kernel<<<blocks, threads>>>((const float4*)input, weight, (float4*)out);
}

// round 4
// speedup vs baseline: 1.0473x; 1.0089x over previous
#include <cuda_runtime.h>

// out[i] = in[i,1] + w*(in[i,0]-in[i,1])
// N = 16777216. Pure streaming, 12 B/elem.
// R3 best (26.3us, DRAM 78.6%): 4 outputs/thread, two LDG.128, __stcs store.
// Only delta vs R3: evict-first loads (__ldcs) — input is read exactly once.

__global__ __launch_bounds__(256)
void skip_kernel(const float4* __restrict__ in,
                 const float* __restrict__ w_ptr,
                 float4* __restrict__ out)
{
    const unsigned i = blockIdx.x * blockDim.x + threadIdx.x;
    const float w = __ldg(w_ptr);

    float4 a = __ldcs(&in[2u * i]);
    float4 b = __ldcs(&in[2u * i + 1u]);

    float4 o;
    o.x = fmaf(w, a.x - a.y, a.y);
    o.y = fmaf(w, a.z - a.w, a.w);
    o.z = fmaf(w, b.x - b.y, b.y);
    o.w = fmaf(w, b.z - b.w, b.w);

    __stcs(&out[i], o);
}

extern "C" void kernel_launch(void* const* d_in, const int* in_sizes, int n_in,
                              void* d_out, int out_size)
{
    const float* input  = (const float*)d_in[0];   // [N,2]
    const float* weight = (const float*)d_in[1];   // [1,1]
    float*       out    = (float*)d_out;           // [N,1]

    const int n = in_sizes[0] / 2;     // 16777216 outputs
    const int n4 = n / 4;              // 4 outputs per thread, exact
    const int threads = 256;
    const int blocks = n4 / threads;   // 16384

    skip_kernel<<<blocks, threads>>>((const float4*)input, weight, (float4*)out);
}